// round 16
// baseline (speedup 1.0000x reference)
#include <cuda_runtime.h>
#include <cuda_bf16.h>
#include <cstdint>

// ---------------- problem constants ----------------
#define NSRC 100000
#define ND0 50000
#define ND1 25000
#define ND2 12500
#define NDT (ND0 + ND1 + ND2)
#define E0  500000
#define E1  250000
#define E2  125000
#define DIM 256
#define NB0 391
#define MAXROWS (NB0 * 128)
#define CAP 128

// ---------------- device scratch (static, no allocs) ----------------
__device__ int g_deg[NDT];
__device__ int g_bkt0[(size_t)ND0 * CAP];
__device__ int g_bkt1[(size_t)ND1 * CAP];
__device__ int g_bkt2[(size_t)ND2 * CAP];
__device__ __align__(16) __nv_bfloat16 g_Amh[(size_t)MAXROWS * DIM];
__device__ __align__(16) __nv_bfloat16 g_Aml[(size_t)MAXROWS * DIM];
__device__ __align__(16) __nv_bfloat16 g_iAh[(size_t)MAXROWS * DIM];
__device__ __align__(16) __nv_bfloat16 g_iAl[(size_t)MAXROWS * DIM];
__device__ __align__(16) __nv_bfloat16 g_iBh[(size_t)MAXROWS * DIM];
__device__ __align__(16) __nv_bfloat16 g_iBl[(size_t)MAXROWS * DIM];
__device__ __align__(16) __nv_bfloat16 g_W[6][2 * 256 * 256];

// ---------------- helpers ----------------
__device__ __forceinline__ uint32_t smem_u32(const void* p) {
    uint32_t a;
    asm("{ .reg .u64 t; cvta.to.shared.u64 t, %1; cvt.u32.u64 %0, t; }" : "=r"(a) : "l"(p));
    return a;
}
__device__ __forceinline__ void cp16(uint32_t dst, const void* src) {
    asm volatile("cp.async.cg.shared.global [%0], [%1], 16;" :: "r"(dst), "l"(src) : "memory");
}
__device__ __forceinline__ void ldmatrix_x4(uint32_t* r, uint32_t addr) {
    asm volatile("ldmatrix.sync.aligned.m8n8.x4.shared.b16 {%0,%1,%2,%3}, [%4];"
                 : "=r"(r[0]), "=r"(r[1]), "=r"(r[2]), "=r"(r[3]) : "r"(addr));
}
__device__ __forceinline__ void ldmatrix_x4_t(uint32_t* r, uint32_t addr) {
    asm volatile("ldmatrix.sync.aligned.m8n8.x4.trans.shared.b16 {%0,%1,%2,%3}, [%4];"
                 : "=r"(r[0]), "=r"(r[1]), "=r"(r[2]), "=r"(r[3]) : "r"(addr));
}
__device__ __forceinline__ void mma_bf16(float* c, const uint32_t* a, uint32_t b0, uint32_t b1) {
    asm volatile(
        "mma.sync.aligned.m16n8k16.row.col.f32.bf16.bf16.f32 "
        "{%0,%1,%2,%3}, {%4,%5,%6,%7}, {%8,%9}, {%0,%1,%2,%3};"
        : "+f"(c[0]), "+f"(c[1]), "+f"(c[2]), "+f"(c[3])
        : "r"(a[0]), "r"(a[1]), "r"(a[2]), "r"(a[3]), "r"(b0), "r"(b1));
}
__device__ __forceinline__ uint32_t pack_hi(float a, float b) {
    return (uint32_t)__bfloat16_as_ushort(__float2bfloat16(a)) |
           ((uint32_t)__bfloat16_as_ushort(__float2bfloat16(b)) << 16);
}
__device__ __forceinline__ uint32_t pack_lo(float a, float b) {
    float ra = a - __bfloat162float(__float2bfloat16(a));
    float rb = b - __bfloat162float(__float2bfloat16(b));
    return (uint32_t)__bfloat16_as_ushort(__float2bfloat16(ra)) |
           ((uint32_t)__bfloat16_as_ushort(__float2bfloat16(rb)) << 16);
}

// ---------------- bucket CSR build ----------------
__global__ void k_bucket(const int* __restrict__ src, const int* __restrict__ dst,
                         int E, int degoff, int* __restrict__ bkt) {
    int i = blockIdx.x * blockDim.x + threadIdx.x;
    if (i < E) {
        int d = dst[i];
        int pos = atomicAdd(&g_deg[degoff + d], 1);
        if (pos < CAP) bkt[(size_t)d * CAP + pos] = src[i];
    }
}

// ---------------- aggregation from fp32 source (layer 0), 2-way unrolled ----------------
__global__ void k_aggregate_f32(const float* __restrict__ h,
                                __nv_bfloat16* __restrict__ mh, __nv_bfloat16* __restrict__ ml,
                                const int* __restrict__ deg, const int* __restrict__ bkt,
                                int n_dst) {
    int gw = (blockIdx.x * blockDim.x + threadIdx.x) >> 5;
    int lane = threadIdx.x & 31;
    if (gw >= n_dst) return;
    int cnt = min(deg[gw], CAP);
    const int* b = bkt + (size_t)gw * CAP;
    float4 p0 = make_float4(0.f, 0.f, 0.f, 0.f);
    float4 p1 = make_float4(0.f, 0.f, 0.f, 0.f);
    float4 q0 = make_float4(0.f, 0.f, 0.f, 0.f);
    float4 q1 = make_float4(0.f, 0.f, 0.f, 0.f);
    int i = 0;
    for (; i + 2 <= cnt; i += 2) {
        int ia = __ldg(&b[i]);
        int ib = __ldg(&b[i + 1]);
        const float4* ra = (const float4*)(h + (size_t)ia * DIM);
        const float4* rb = (const float4*)(h + (size_t)ib * DIM);
        float4 xa0 = __ldg(&ra[lane]);
        float4 xb0 = __ldg(&rb[lane]);
        float4 xa1 = __ldg(&ra[lane + 32]);
        float4 xb1 = __ldg(&rb[lane + 32]);
        p0.x += xa0.x; p0.y += xa0.y; p0.z += xa0.z; p0.w += xa0.w;
        q0.x += xb0.x; q0.y += xb0.y; q0.z += xb0.z; q0.w += xb0.w;
        p1.x += xa1.x; p1.y += xa1.y; p1.z += xa1.z; p1.w += xa1.w;
        q1.x += xb1.x; q1.y += xb1.y; q1.z += xb1.z; q1.w += xb1.w;
    }
    if (i < cnt) {
        const float4* ra = (const float4*)(h + (size_t)__ldg(&b[i]) * DIM);
        float4 xa0 = __ldg(&ra[lane]);
        float4 xa1 = __ldg(&ra[lane + 32]);
        p0.x += xa0.x; p0.y += xa0.y; p0.z += xa0.z; p0.w += xa0.w;
        p1.x += xa1.x; p1.y += xa1.y; p1.z += xa1.z; p1.w += xa1.w;
    }
    float inv = 1.0f / (float)max(cnt, 1);
    float4 a0, a1;
    a0.x = (p0.x + q0.x) * inv; a0.y = (p0.y + q0.y) * inv;
    a0.z = (p0.z + q0.z) * inv; a0.w = (p0.w + q0.w) * inv;
    a1.x = (p1.x + q1.x) * inv; a1.y = (p1.y + q1.y) * inv;
    a1.z = (p1.z + q1.z) * inv; a1.w = (p1.w + q1.w) * inv;
    size_t off0 = (size_t)gw * DIM + lane * 4;
    size_t off1 = off0 + 128;
    *(uint2*)(mh + off0) = make_uint2(pack_hi(a0.x, a0.y), pack_hi(a0.z, a0.w));
    *(uint2*)(ml + off0) = make_uint2(pack_lo(a0.x, a0.y), pack_lo(a0.z, a0.w));
    *(uint2*)(mh + off1) = make_uint2(pack_hi(a1.x, a1.y), pack_hi(a1.z, a1.w));
    *(uint2*)(ml + off1) = make_uint2(pack_lo(a1.x, a1.y), pack_lo(a1.z, a1.w));
}

// ---------------- aggregation from bf16 hi/lo images (layers 1,2), 2-way unrolled ----------------
__global__ void k_aggregate_bf16(const __nv_bfloat16* __restrict__ hh, const __nv_bfloat16* __restrict__ hl,
                                 __nv_bfloat16* __restrict__ mh, __nv_bfloat16* __restrict__ ml,
                                 const int* __restrict__ deg, const int* __restrict__ bkt,
                                 int n_dst) {
    int gw = (blockIdx.x * blockDim.x + threadIdx.x) >> 5;
    int lane = threadIdx.x & 31;
    if (gw >= n_dst) return;
    int cnt = min(deg[gw], CAP);
    const int* b = bkt + (size_t)gw * CAP;
    float accA[8] = {0.f, 0.f, 0.f, 0.f, 0.f, 0.f, 0.f, 0.f};
    float accB[8] = {0.f, 0.f, 0.f, 0.f, 0.f, 0.f, 0.f, 0.f};
    int i = 0;
    for (; i + 2 <= cnt; i += 2) {
        size_t roa = (size_t)__ldg(&b[i]) * DIM + lane * 8;
        size_t rob = (size_t)__ldg(&b[i + 1]) * DIM + lane * 8;
        uint4 vha = __ldg((const uint4*)(hh + roa));
        uint4 vhb = __ldg((const uint4*)(hh + rob));
        uint4 vla = __ldg((const uint4*)(hl + roa));
        uint4 vlb = __ldg((const uint4*)(hl + rob));
        const uint32_t* pha = &vha.x;
        const uint32_t* pla = &vla.x;
        const uint32_t* phb = &vhb.x;
        const uint32_t* plb = &vlb.x;
        #pragma unroll
        for (int q = 0; q < 4; q++) {
            float2 fha = __bfloat1622float2(*(const __nv_bfloat162*)&pha[q]);
            float2 fla = __bfloat1622float2(*(const __nv_bfloat162*)&pla[q]);
            float2 fhb = __bfloat1622float2(*(const __nv_bfloat162*)&phb[q]);
            float2 flb = __bfloat1622float2(*(const __nv_bfloat162*)&plb[q]);
            accA[2 * q + 0] += fha.x + fla.x;
            accA[2 * q + 1] += fha.y + fla.y;
            accB[2 * q + 0] += fhb.x + flb.x;
            accB[2 * q + 1] += fhb.y + flb.y;
        }
    }
    if (i < cnt) {
        size_t ro = (size_t)__ldg(&b[i]) * DIM + lane * 8;
        uint4 vh = __ldg((const uint4*)(hh + ro));
        uint4 vl = __ldg((const uint4*)(hl + ro));
        const uint32_t* ph = &vh.x;
        const uint32_t* pl = &vl.x;
        #pragma unroll
        for (int q = 0; q < 4; q++) {
            float2 fh = __bfloat1622float2(*(const __nv_bfloat162*)&ph[q]);
            float2 fl = __bfloat1622float2(*(const __nv_bfloat162*)&pl[q]);
            accA[2 * q + 0] += fh.x + fl.x;
            accA[2 * q + 1] += fh.y + fl.y;
        }
    }
    float inv = 1.0f / (float)max(cnt, 1);
    float acc[8];
    #pragma unroll
    for (int q = 0; q < 8; q++) acc[q] = (accA[q] + accB[q]) * inv;
    size_t off = (size_t)gw * DIM + lane * 8;
    *(uint4*)(mh + off) = make_uint4(pack_hi(acc[0], acc[1]), pack_hi(acc[2], acc[3]),
                                     pack_hi(acc[4], acc[5]), pack_hi(acc[6], acc[7]));
    *(uint4*)(ml + off) = make_uint4(pack_lo(acc[0], acc[1]), pack_lo(acc[2], acc[3]),
                                     pack_lo(acc[4], acc[5]), pack_lo(acc[6], acc[7]));
}

// ---------------- fp32 -> bf16 hi/lo images ----------------
__global__ void k_convert(const float* __restrict__ src, __nv_bfloat16* __restrict__ hi,
                          __nv_bfloat16* __restrict__ lo, int n_rows) {
    int t = blockIdx.x * blockDim.x + threadIdx.x;
    if (t >= n_rows * 32) return;
    int row = t >> 5, seg = t & 31;
    const float4* p = (const float4*)(src + (size_t)row * DIM + seg * 8);
    float4 v0 = p[0], v1 = p[1];
    size_t off = (size_t)row * DIM + seg * 8;
    *(uint4*)(hi + off) = make_uint4(pack_hi(v0.x, v0.y), pack_hi(v0.z, v0.w),
                                     pack_hi(v1.x, v1.y), pack_hi(v1.z, v1.w));
    *(uint4*)(lo + off) = make_uint4(pack_lo(v0.x, v0.y), pack_lo(v0.z, v0.w),
                                     pack_lo(v1.x, v1.y), pack_lo(v1.z, v1.w));
}

// ---------------- all 6 weights -> hi/lo images ----------------
__global__ void k_wconvert_all(const float* __restrict__ w0, const float* __restrict__ w1,
                               const float* __restrict__ w2, const float* __restrict__ w3,
                               const float* __restrict__ w4, const float* __restrict__ w5) {
    int t = blockIdx.x * blockDim.x + threadIdx.x;
    int wi, rem, N;
    if (t < 4 * 8192) { wi = t >> 13; rem = t & 8191; N = 256; }
    else if (t < 4 * 8192 + 2 * 4096) { int u = t - 4 * 8192; wi = 4 + (u >> 12); rem = u & 4095; N = 128; }
    else return;
    const float* W = (wi == 0) ? w0 : (wi == 1) ? w1 : (wi == 2) ? w2 : (wi == 3) ? w3 : (wi == 4) ? w4 : w5;
    int nseg = N >> 3;
    int k = rem / nseg, seg = rem % nseg;
    const float4* p = (const float4*)(W + (size_t)k * N + seg * 8);
    float4 v0 = p[0], v1 = p[1];
    __nv_bfloat16* dst = &g_W[wi][0];
    size_t off = (size_t)k * N + seg * 8;
    *(uint4*)(dst + off) = make_uint4(pack_hi(v0.x, v0.y), pack_hi(v0.z, v0.w),
                                      pack_hi(v1.x, v1.y), pack_hi(v1.z, v1.w));
    *(uint4*)(dst + (size_t)256 * N + off) = make_uint4(pack_lo(v0.x, v0.y), pack_lo(v0.z, v0.w),
                                                        pack_lo(v1.x, v1.y), pack_lo(v1.z, v1.w));
}

// ---------------- mma.sync bf16 GEMM, dual-B passes, 4-stage cp.async ----------------
#define ASTRIDE_B 80
#define BSTRIDE_B 272
#define ABYTES (128 * ASTRIDE_B)
#define BBYTES (32 * BSTRIDE_B)
#define STAGEB (ABYTES + 2 * BBYTES)
#define STAGES 4
#define SMEM_TOT (STAGES * STAGEB)

__global__ void __launch_bounds__(256, 2) k_gemm_mma(
    const __nv_bfloat16* __restrict__ Amh, const __nv_bfloat16* __restrict__ Aml,
    const __nv_bfloat16* __restrict__ Ash, const __nv_bfloat16* __restrict__ Asl,
    const __nv_bfloat16* __restrict__ Wn, const __nv_bfloat16* __restrict__ Ws,
    const float* __restrict__ bias, float* __restrict__ out,
    __nv_bfloat16* __restrict__ selfH, __nv_bfloat16* __restrict__ selfL,
    int M, int N, int relu)
{
    extern __shared__ __align__(16) char smem[];
    int tid = threadIdx.x, lane = tid & 31, wid = tid >> 5;
    int warp_m = wid >> 2, warp_n = wid & 3;
    int blkN = blockIdx.x, blkM = blockIdx.y;

    size_t wlo = (size_t)256 * N;
    const __nv_bfloat16* Ap[4]  = {Amh, Aml, Ash, Asl};
    const __nv_bfloat16* B0p[4] = {Wn, Wn, Ws, Ws};
    const __nv_bfloat16* B1p[4] = {Wn + wlo, Wn, Ws + wlo, Ws};

    int rowA = tid >> 2, segA = tid & 3;
    int rowB = tid >> 4, segB = tid & 15;
    size_t gA0 = ((size_t)(blkM * 128 + rowA)) * DIM + segA * 8;
    size_t gA1 = gA0 + (size_t)64 * DIM;
    size_t gB0 = (size_t)rowB * N + blkN * 128 + segB * 8;
    size_t gB1 = gB0 + (size_t)16 * N;
    uint32_t sb = smem_u32(smem);
    uint32_t sA0 = (uint32_t)(rowA * ASTRIDE_B + segA * 16);
    uint32_t sA1 = sA0 + 64 * ASTRIDE_B;
    uint32_t sB0 = (uint32_t)(ABYTES + rowB * BSTRIDE_B + segB * 16);
    uint32_t sB1 = sB0 + 16 * BSTRIDE_B;

    float acc[4][4][4];
    #pragma unroll
    for (int m = 0; m < 4; m++)
        #pragma unroll
        for (int n = 0; n < 4; n++)
            #pragma unroll
            for (int k = 0; k < 4; k++) acc[m][n][k] = 0.f;

    uint32_t aBase  = (uint32_t)((warp_m * 64 + (lane & 15)) * ASTRIDE_B + (lane >> 4) * 16);
    uint32_t b0Base = (uint32_t)(ABYTES + (lane & 15) * BSTRIDE_B + (lane >> 4) * 16 + warp_n * 64);

    #define ISSUE(it) do {                                              \
        int _p = (it) >> 3, _kk = (it) & 7;                             \
        int _dual = !(_p & 1);                                          \
        uint32_t _d = sb + ((it) % STAGES) * STAGEB;                    \
        const __nv_bfloat16* _Ag = Ap[_p] + _kk * 32;                   \
        const __nv_bfloat16* _Bg0 = B0p[_p] + (size_t)_kk * 32 * N;     \
        cp16(_d + sA0, _Ag + gA0);                                      \
        cp16(_d + sA1, _Ag + gA1);                                      \
        cp16(_d + sB0, _Bg0 + gB0);                                     \
        cp16(_d + sB1, _Bg0 + gB1);                                     \
        if (_dual) {                                                    \
            const __nv_bfloat16* _Bg1 = B1p[_p] + (size_t)_kk * 32 * N; \
            cp16(_d + sB0 + BBYTES, _Bg1 + gB0);                        \
            cp16(_d + sB1 + BBYTES, _Bg1 + gB1);                        \
        }                                                               \
        asm volatile("cp.async.commit_group;" ::: "memory");            \
    } while (0)

    ISSUE(0);
    ISSUE(1);
    ISSUE(2);
    for (int it = 0; it < 32; ++it) {
        asm volatile("cp.async.wait_group 2;" ::: "memory");
        __syncthreads();
        if (it + 3 < 32) ISSUE(it + 3);
        uint32_t base = sb + (it % STAGES) * STAGEB;
        int dual = !((it >> 3) & 1);
        #pragma unroll
        for (int ks = 0; ks < 2; ks++) {
            uint32_t a[4][4], b0[2][4];
            #pragma unroll
            for (int m = 0; m < 4; m++)
                ldmatrix_x4(a[m], base + aBase + m * 16 * ASTRIDE_B + ks * 32);
            #pragma unroll
            for (int n2 = 0; n2 < 2; n2++)
                ldmatrix_x4_t(b0[n2], base + b0Base + n2 * 32 + ks * 16 * BSTRIDE_B);
            #pragma unroll
            for (int m = 0; m < 4; m++) {
                #pragma unroll
                for (int n2 = 0; n2 < 2; n2++) {
                    mma_bf16(acc[m][2 * n2 + 0], a[m], b0[n2][0], b0[n2][1]);
                    mma_bf16(acc[m][2 * n2 + 1], a[m], b0[n2][2], b0[n2][3]);
                }
            }
            if (dual) {
                uint32_t b1[2][4];
                #pragma unroll
                for (int n2 = 0; n2 < 2; n2++)
                    ldmatrix_x4_t(b1[n2], base + b0Base + BBYTES + n2 * 32 + ks * 16 * BSTRIDE_B);
                #pragma unroll
                for (int m = 0; m < 4; m++) {
                    #pragma unroll
                    for (int n2 = 0; n2 < 2; n2++) {
                        mma_bf16(acc[m][2 * n2 + 0], a[m], b1[n2][0], b1[n2][1]);
                        mma_bf16(acc[m][2 * n2 + 1], a[m], b1[n2][2], b1[n2][3]);
                    }
                }
            }
        }
    }

    #pragma unroll
    for (int m = 0; m < 4; m++) {
        int row0 = blkM * 128 + warp_m * 64 + m * 16 + (lane >> 2);
        int row1 = row0 + 8;
        #pragma unroll
        for (int n = 0; n < 4; n++) {
            int col = blkN * 128 + warp_n * 32 + n * 8 + (lane & 3) * 2;
            float bv0 = bias[col], bv1 = bias[col + 1];
            float v0 = acc[m][n][0] + bv0, v1 = acc[m][n][1] + bv1;
            float v2 = acc[m][n][2] + bv0, v3 = acc[m][n][3] + bv1;
            if (relu) {
                v0 = fmaxf(v0, 0.f); v1 = fmaxf(v1, 0.f);
                v2 = fmaxf(v2, 0.f); v3 = fmaxf(v3, 0.f);
            }
            if (row0 < M) {
                if (out) *(float2*)(out + (size_t)row0 * N + col) = make_float2(v0, v1);
                if (selfH) {
                    *(uint32_t*)(selfH + (size_t)row0 * N + col) = pack_hi(v0, v1);
                    *(uint32_t*)(selfL + (size_t)row0 * N + col) = pack_lo(v0, v1);
                }
            }
            if (row1 < M) {
                if (out) *(float2*)(out + (size_t)row1 * N + col) = make_float2(v2, v3);
                if (selfH) {
                    *(uint32_t*)(selfH + (size_t)row1 * N + col) = pack_hi(v2, v3);
                    *(uint32_t*)(selfL + (size_t)row1 * N + col) = pack_lo(v2, v3);
                }
            }
        }
    }
}

// ---------------- host orchestration ----------------
extern "C" void kernel_launch(void* const* d_in, const int* in_sizes, int n_in,
                              void* d_out, int out_size)
{
    const float* x   = (const float*)d_in[0];
    const float* Wn0 = (const float*)d_in[1];
    const float* Ws0 = (const float*)d_in[2];
    const float* b0  = (const float*)d_in[3];
    const float* Wn1 = (const float*)d_in[4];
    const float* Ws1 = (const float*)d_in[5];
    const float* b1  = (const float*)d_in[6];
    const float* Wn2 = (const float*)d_in[7];
    const float* Ws2 = (const float*)d_in[8];
    const float* b2  = (const float*)d_in[9];
    const int* src0 = (const int*)d_in[10];
    const int* dst0 = (const int*)d_in[11];
    const int* src1 = (const int*)d_in[12];
    const int* dst1 = (const int*)d_in[13];
    const int* src2 = (const int*)d_in[14];
    const int* dst2 = (const int*)d_in[15];
    (void)in_sizes; (void)n_in; (void)out_size;

    static cudaStream_t s2 = nullptr;
    static cudaEvent_t ev0 = nullptr, evM = nullptr, evC = nullptr, evG = nullptr;
    if (!s2) {
        cudaStreamCreateWithFlags(&s2, cudaStreamNonBlocking);
        cudaEventCreateWithFlags(&ev0, cudaEventDisableTiming);
        cudaEventCreateWithFlags(&evM, cudaEventDisableTiming);
        cudaEventCreateWithFlags(&evC, cudaEventDisableTiming);
        cudaEventCreateWithFlags(&evG, cudaEventDisableTiming);
        cudaFuncSetAttribute(k_gemm_mma, cudaFuncAttributeMaxDynamicSharedMemorySize, SMEM_TOT);
    }

    __nv_bfloat16 *p_Amh, *p_Aml, *p_iAh, *p_iAl, *p_iBh, *p_iBl, *p_W;
    int *p_deg, *p_b0, *p_b1, *p_b2;
    cudaGetSymbolAddress((void**)&p_Amh, g_Amh);
    cudaGetSymbolAddress((void**)&p_Aml, g_Aml);
    cudaGetSymbolAddress((void**)&p_iAh, g_iAh);
    cudaGetSymbolAddress((void**)&p_iAl, g_iAl);
    cudaGetSymbolAddress((void**)&p_iBh, g_iBh);
    cudaGetSymbolAddress((void**)&p_iBl, g_iBl);
    cudaGetSymbolAddress((void**)&p_W, g_W);
    cudaGetSymbolAddress((void**)&p_deg, g_deg);
    cudaGetSymbolAddress((void**)&p_b0, g_bkt0);
    cudaGetSymbolAddress((void**)&p_b1, g_bkt1);
    cudaGetSymbolAddress((void**)&p_b2, g_bkt2);
    __nv_bfloat16* Wimg[6];
    for (int i = 0; i < 6; i++) Wimg[i] = p_W + (size_t)i * (2 * 256 * 256);

    // ---- fork ----
    cudaEventRecord(ev0, 0);
    cudaStreamWaitEvent(s2, ev0, 0);

    // main: deg zero + bucket0 + agg0 (fp32 x gather)
    cudaMemsetAsync(p_deg, 0, sizeof(int) * NDT, 0);
    cudaEventRecord(evM, 0);
    k_bucket<<<(E0 + 255) / 256, 256>>>(src0, dst0, E0, 0, p_b0);
    k_aggregate_f32<<<(ND0 + 7) / 8, 256>>>(x, p_Amh, p_Aml, p_deg, p_b0, ND0);

    // side: converts (weights + x[:ND0] self image), then buckets 1+2
    k_wconvert_all<<<(4 * 8192 + 2 * 4096 + 255) / 256, 256, 0, s2>>>(Wn0, Ws0, Wn1, Ws1, Wn2, Ws2);
    k_convert<<<(ND0 * 32 + 255) / 256, 256, 0, s2>>>(x, p_iAh, p_iAl, ND0);
    cudaEventRecord(evC, s2);
    cudaStreamWaitEvent(s2, evM, 0);
    k_bucket<<<(E1 + 255) / 256, 256, 0, s2>>>(src1, dst1, E1, ND0, p_b1);
    k_bucket<<<(E2 + 255) / 256, 256, 0, s2>>>(src2, dst2, E2, ND0 + ND1, p_b2);
    cudaEventRecord(evG, s2);

    // main: layer 0 GEMM (needs x self images + weights from evC)
    cudaStreamWaitEvent(0, evC, 0);
    {
        dim3 grid(2, (ND0 + 127) / 128);
        k_gemm_mma<<<grid, 256, SMEM_TOT>>>(p_Amh, p_Aml, p_iAh, p_iAl, Wimg[0], Wimg[1],
                                            b0, nullptr, p_iBh, p_iBl, ND0, 256, 1);
    }
    // main: layers 1,2 (need buckets 1+2 from evG)
    cudaStreamWaitEvent(0, evG, 0);
    k_aggregate_bf16<<<(ND1 + 7) / 8, 256>>>(p_iBh, p_iBl, p_Amh, p_Aml, p_deg + ND0, p_b1, ND1);
    {
        dim3 grid(2, (ND1 + 127) / 128);
        k_gemm_mma<<<grid, 256, SMEM_TOT>>>(p_Amh, p_Aml, p_iBh, p_iBl, Wimg[2], Wimg[3],
                                            b1, nullptr, p_iAh, p_iAl, ND1, 256, 1);
    }
    k_aggregate_bf16<<<(ND2 + 7) / 8, 256>>>(p_iAh, p_iAl, p_Amh, p_Aml, p_deg + ND0 + ND1, p_b2, ND2);
    {
        dim3 grid(1, (ND2 + 127) / 128);
        k_gemm_mma<<<grid, 256, SMEM_TOT>>>(p_Amh, p_Aml, p_iAh, p_iAl, Wimg[4], Wimg[5],
                                            b2, (float*)d_out, nullptr, nullptr, ND2, 128, 0);
    }
}

// round 17
// speedup vs baseline: 1.0254x; 1.0254x over previous
#include <cuda_runtime.h>
#include <cuda_bf16.h>
#include <cstdint>

// ---------------- problem constants ----------------
#define NSRC 100000
#define ND0 50000
#define ND1 25000
#define ND2 12500
#define NDT (ND0 + ND1 + ND2)
#define E0  500000
#define E1  250000
#define E2  125000
#define DIM 256
#define NB0 391
#define MAXROWS (NB0 * 128)
#define CAP 64               // bucket capacity (Poisson(10): P(deg>64) ~ 1e-30)

// ---------------- device scratch (static, no allocs) ----------------
__device__ int g_deg[NDT];
__device__ int g_bkt0[(size_t)ND0 * CAP];
__device__ int g_bkt1[(size_t)ND1 * CAP];
__device__ int g_bkt2[(size_t)ND2 * CAP];
__device__ __align__(16) __nv_bfloat16 g_Amh[(size_t)MAXROWS * DIM];
__device__ __align__(16) __nv_bfloat16 g_Aml[(size_t)MAXROWS * DIM];
__device__ __align__(16) __nv_bfloat16 g_iAh[(size_t)MAXROWS * DIM];
__device__ __align__(16) __nv_bfloat16 g_iAl[(size_t)MAXROWS * DIM];
__device__ __align__(16) __nv_bfloat16 g_iBh[(size_t)MAXROWS * DIM];
__device__ __align__(16) __nv_bfloat16 g_iBl[(size_t)MAXROWS * DIM];
__device__ __align__(16) __nv_bfloat16 g_W[6][2 * 256 * 256];

// ---------------- helpers ----------------
__device__ __forceinline__ uint32_t smem_u32(const void* p) {
    uint32_t a;
    asm("{ .reg .u64 t; cvta.to.shared.u64 t, %1; cvt.u32.u64 %0, t; }" : "=r"(a) : "l"(p));
    return a;
}
__device__ __forceinline__ void cp16(uint32_t dst, const void* src) {
    asm volatile("cp.async.cg.shared.global [%0], [%1], 16;" :: "r"(dst), "l"(src) : "memory");
}
__device__ __forceinline__ void ldmatrix_x4(uint32_t* r, uint32_t addr) {
    asm volatile("ldmatrix.sync.aligned.m8n8.x4.shared.b16 {%0,%1,%2,%3}, [%4];"
                 : "=r"(r[0]), "=r"(r[1]), "=r"(r[2]), "=r"(r[3]) : "r"(addr));
}
__device__ __forceinline__ void ldmatrix_x4_t(uint32_t* r, uint32_t addr) {
    asm volatile("ldmatrix.sync.aligned.m8n8.x4.trans.shared.b16 {%0,%1,%2,%3}, [%4];"
                 : "=r"(r[0]), "=r"(r[1]), "=r"(r[2]), "=r"(r[3]) : "r"(addr));
}
__device__ __forceinline__ void mma_bf16(float* c, const uint32_t* a, uint32_t b0, uint32_t b1) {
    asm volatile(
        "mma.sync.aligned.m16n8k16.row.col.f32.bf16.bf16.f32 "
        "{%0,%1,%2,%3}, {%4,%5,%6,%7}, {%8,%9}, {%0,%1,%2,%3};"
        : "+f"(c[0]), "+f"(c[1]), "+f"(c[2]), "+f"(c[3])
        : "r"(a[0]), "r"(a[1]), "r"(a[2]), "r"(a[3]), "r"(b0), "r"(b1));
}
__device__ __forceinline__ uint32_t pack_hi(float a, float b) {
    return (uint32_t)__bfloat16_as_ushort(__float2bfloat16(a)) |
           ((uint32_t)__bfloat16_as_ushort(__float2bfloat16(b)) << 16);
}
__device__ __forceinline__ uint32_t pack_lo(float a, float b) {
    float ra = a - __bfloat162float(__float2bfloat16(a));
    float rb = b - __bfloat162float(__float2bfloat16(b));
    return (uint32_t)__bfloat16_as_ushort(__float2bfloat16(ra)) |
           ((uint32_t)__bfloat16_as_ushort(__float2bfloat16(rb)) << 16);
}

// ---------------- bucket CSR build ----------------
__global__ void k_bucket(const int* __restrict__ src, const int* __restrict__ dst,
                         int E, int degoff, int* __restrict__ bkt) {
    int i = blockIdx.x * blockDim.x + threadIdx.x;
    if (i < E) {
        int d = dst[i];
        int pos = atomicAdd(&g_deg[degoff + d], 1);
        if (pos < CAP) bkt[((size_t)d << 6) + pos] = src[i];
    }
}

// ---------------- aggregation from fp32 source (layer 0) ----------------
__global__ void k_aggregate_f32(const float* __restrict__ h,
                                __nv_bfloat16* __restrict__ mh, __nv_bfloat16* __restrict__ ml,
                                const int* __restrict__ deg, const int* __restrict__ bkt,
                                int n_dst) {
    int gw = (blockIdx.x * blockDim.x + threadIdx.x) >> 5;
    int lane = threadIdx.x & 31;
    if (gw >= n_dst) return;
    int cnt = min(deg[gw], CAP);
    const int* b = bkt + ((size_t)gw << 6);
    float4 a0 = make_float4(0.f, 0.f, 0.f, 0.f);
    float4 a1 = make_float4(0.f, 0.f, 0.f, 0.f);
    for (int i = 0; i < cnt; i++) {
        const float4* row = (const float4*)(h + (size_t)__ldg(&b[i]) * DIM);
        float4 x0 = __ldg(&row[lane]);
        float4 x1 = __ldg(&row[lane + 32]);
        a0.x += x0.x; a0.y += x0.y; a0.z += x0.z; a0.w += x0.w;
        a1.x += x1.x; a1.y += x1.y; a1.z += x1.z; a1.w += x1.w;
    }
    float inv = 1.0f / (float)max(cnt, 1);
    a0.x *= inv; a0.y *= inv; a0.z *= inv; a0.w *= inv;
    a1.x *= inv; a1.y *= inv; a1.z *= inv; a1.w *= inv;
    size_t off0 = (size_t)gw * DIM + lane * 4;
    size_t off1 = off0 + 128;
    *(uint2*)(mh + off0) = make_uint2(pack_hi(a0.x, a0.y), pack_hi(a0.z, a0.w));
    *(uint2*)(ml + off0) = make_uint2(pack_lo(a0.x, a0.y), pack_lo(a0.z, a0.w));
    *(uint2*)(mh + off1) = make_uint2(pack_hi(a1.x, a1.y), pack_hi(a1.z, a1.w));
    *(uint2*)(ml + off1) = make_uint2(pack_lo(a1.x, a1.y), pack_lo(a1.z, a1.w));
}

// ---------------- aggregation from bf16 hi/lo images (layers 1,2) ----------------
__global__ void k_aggregate_bf16(const __nv_bfloat16* __restrict__ hh, const __nv_bfloat16* __restrict__ hl,
                                 __nv_bfloat16* __restrict__ mh, __nv_bfloat16* __restrict__ ml,
                                 const int* __restrict__ deg, const int* __restrict__ bkt,
                                 int n_dst) {
    int gw = (blockIdx.x * blockDim.x + threadIdx.x) >> 5;
    int lane = threadIdx.x & 31;
    if (gw >= n_dst) return;
    int cnt = min(deg[gw], CAP);
    const int* b = bkt + ((size_t)gw << 6);
    float acc[8] = {0.f, 0.f, 0.f, 0.f, 0.f, 0.f, 0.f, 0.f};
    for (int i = 0; i < cnt; i++) {
        size_t ro = (size_t)__ldg(&b[i]) * DIM + lane * 8;
        uint4 vh = __ldg((const uint4*)(hh + ro));
        uint4 vl = __ldg((const uint4*)(hl + ro));
        const uint32_t* ph = &vh.x;
        const uint32_t* pl = &vl.x;
        #pragma unroll
        for (int q = 0; q < 4; q++) {
            float2 fh = __bfloat1622float2(*(const __nv_bfloat162*)&ph[q]);
            float2 fl = __bfloat1622float2(*(const __nv_bfloat162*)&pl[q]);
            acc[2 * q + 0] += fh.x + fl.x;
            acc[2 * q + 1] += fh.y + fl.y;
        }
    }
    float inv = 1.0f / (float)max(cnt, 1);
    #pragma unroll
    for (int q = 0; q < 8; q++) acc[q] *= inv;
    size_t off = (size_t)gw * DIM + lane * 8;
    *(uint4*)(mh + off) = make_uint4(pack_hi(acc[0], acc[1]), pack_hi(acc[2], acc[3]),
                                     pack_hi(acc[4], acc[5]), pack_hi(acc[6], acc[7]));
    *(uint4*)(ml + off) = make_uint4(pack_lo(acc[0], acc[1]), pack_lo(acc[2], acc[3]),
                                     pack_lo(acc[4], acc[5]), pack_lo(acc[6], acc[7]));
}

// ---------------- fp32 -> bf16 hi/lo images ----------------
__global__ void k_convert(const float* __restrict__ src, __nv_bfloat16* __restrict__ hi,
                          __nv_bfloat16* __restrict__ lo, int n_rows) {
    int t = blockIdx.x * blockDim.x + threadIdx.x;
    if (t >= n_rows * 32) return;
    int row = t >> 5, seg = t & 31;
    const float4* p = (const float4*)(src + (size_t)row * DIM + seg * 8);
    float4 v0 = p[0], v1 = p[1];
    size_t off = (size_t)row * DIM + seg * 8;
    *(uint4*)(hi + off) = make_uint4(pack_hi(v0.x, v0.y), pack_hi(v0.z, v0.w),
                                     pack_hi(v1.x, v1.y), pack_hi(v1.z, v1.w));
    *(uint4*)(lo + off) = make_uint4(pack_lo(v0.x, v0.y), pack_lo(v0.z, v0.w),
                                     pack_lo(v1.x, v1.y), pack_lo(v1.z, v1.w));
}

// ---------------- all 6 weights -> hi/lo images ----------------
__global__ void k_wconvert_all(const float* __restrict__ w0, const float* __restrict__ w1,
                               const float* __restrict__ w2, const float* __restrict__ w3,
                               const float* __restrict__ w4, const float* __restrict__ w5) {
    int t = blockIdx.x * blockDim.x + threadIdx.x;
    int wi, rem, N;
    if (t < 4 * 8192) { wi = t >> 13; rem = t & 8191; N = 256; }
    else if (t < 4 * 8192 + 2 * 4096) { int u = t - 4 * 8192; wi = 4 + (u >> 12); rem = u & 4095; N = 128; }
    else return;
    const float* W = (wi == 0) ? w0 : (wi == 1) ? w1 : (wi == 2) ? w2 : (wi == 3) ? w3 : (wi == 4) ? w4 : w5;
    int nseg = N >> 3;
    int k = rem / nseg, seg = rem % nseg;
    const float4* p = (const float4*)(W + (size_t)k * N + seg * 8);
    float4 v0 = p[0], v1 = p[1];
    __nv_bfloat16* dst = &g_W[wi][0];
    size_t off = (size_t)k * N + seg * 8;
    *(uint4*)(dst + off) = make_uint4(pack_hi(v0.x, v0.y), pack_hi(v0.z, v0.w),
                                      pack_hi(v1.x, v1.y), pack_hi(v1.z, v1.w));
    *(uint4*)(dst + (size_t)256 * N + off) = make_uint4(pack_lo(v0.x, v0.y), pack_lo(v0.z, v0.w),
                                                        pack_lo(v1.x, v1.y), pack_lo(v1.z, v1.w));
}

// ---------------- mma.sync bf16 GEMM, dual-B passes, 4-stage cp.async ----------------
#define ASTRIDE_B 80
#define BSTRIDE_B 272
#define ABYTES (128 * ASTRIDE_B)
#define BBYTES (32 * BSTRIDE_B)
#define STAGEB (ABYTES + 2 * BBYTES)
#define STAGES 4
#define SMEM_TOT (STAGES * STAGEB)

__global__ void __launch_bounds__(256, 2) k_gemm_mma(
    const __nv_bfloat16* __restrict__ Amh, const __nv_bfloat16* __restrict__ Aml,
    const __nv_bfloat16* __restrict__ Ash, const __nv_bfloat16* __restrict__ Asl,
    const __nv_bfloat16* __restrict__ Wn, const __nv_bfloat16* __restrict__ Ws,
    const float* __restrict__ bias, float* __restrict__ out,
    __nv_bfloat16* __restrict__ selfH, __nv_bfloat16* __restrict__ selfL,
    int M, int N, int relu)
{
    extern __shared__ __align__(16) char smem[];
    int tid = threadIdx.x, lane = tid & 31, wid = tid >> 5;
    int warp_m = wid >> 2, warp_n = wid & 3;
    int blkN = blockIdx.x, blkM = blockIdx.y;

    size_t wlo = (size_t)256 * N;
    const __nv_bfloat16* Ap[4]  = {Amh, Aml, Ash, Asl};
    const __nv_bfloat16* B0p[4] = {Wn, Wn, Ws, Ws};
    const __nv_bfloat16* B1p[4] = {Wn + wlo, Wn, Ws + wlo, Ws};

    int rowA = tid >> 2, segA = tid & 3;
    int rowB = tid >> 4, segB = tid & 15;
    size_t gA0 = ((size_t)(blkM * 128 + rowA)) * DIM + segA * 8;
    size_t gA1 = gA0 + (size_t)64 * DIM;
    size_t gB0 = (size_t)rowB * N + blkN * 128 + segB * 8;
    size_t gB1 = gB0 + (size_t)16 * N;
    uint32_t sb = smem_u32(smem);
    uint32_t sA0 = (uint32_t)(rowA * ASTRIDE_B + segA * 16);
    uint32_t sA1 = sA0 + 64 * ASTRIDE_B;
    uint32_t sB0 = (uint32_t)(ABYTES + rowB * BSTRIDE_B + segB * 16);
    uint32_t sB1 = sB0 + 16 * BSTRIDE_B;

    float acc[4][4][4];
    #pragma unroll
    for (int m = 0; m < 4; m++)
        #pragma unroll
        for (int n = 0; n < 4; n++)
            #pragma unroll
            for (int k = 0; k < 4; k++) acc[m][n][k] = 0.f;

    uint32_t aBase  = (uint32_t)((warp_m * 64 + (lane & 15)) * ASTRIDE_B + (lane >> 4) * 16);
    uint32_t b0Base = (uint32_t)(ABYTES + (lane & 15) * BSTRIDE_B + (lane >> 4) * 16 + warp_n * 64);

    #define ISSUE(it) do {                                              \
        int _p = (it) >> 3, _kk = (it) & 7;                             \
        int _dual = !(_p & 1);                                          \
        uint32_t _d = sb + ((it) % STAGES) * STAGEB;                    \
        const __nv_bfloat16* _Ag = Ap[_p] + _kk * 32;                   \
        const __nv_bfloat16* _Bg0 = B0p[_p] + (size_t)_kk * 32 * N;     \
        cp16(_d + sA0, _Ag + gA0);                                      \
        cp16(_d + sA1, _Ag + gA1);                                      \
        cp16(_d + sB0, _Bg0 + gB0);                                     \
        cp16(_d + sB1, _Bg0 + gB1);                                     \
        if (_dual) {                                                    \
            const __nv_bfloat16* _Bg1 = B1p[_p] + (size_t)_kk * 32 * N; \
            cp16(_d + sB0 + BBYTES, _Bg1 + gB0);                        \
            cp16(_d + sB1 + BBYTES, _Bg1 + gB1);                        \
        }                                                               \
        asm volatile("cp.async.commit_group;" ::: "memory");            \
    } while (0)

    ISSUE(0);
    ISSUE(1);
    ISSUE(2);
    for (int it = 0; it < 32; ++it) {
        asm volatile("cp.async.wait_group 2;" ::: "memory");
        __syncthreads();
        if (it + 3 < 32) ISSUE(it + 3);
        uint32_t base = sb + (it % STAGES) * STAGEB;
        int dual = !((it >> 3) & 1);
        #pragma unroll
        for (int ks = 0; ks < 2; ks++) {
            uint32_t a[4][4], b0[2][4];
            #pragma unroll
            for (int m = 0; m < 4; m++)
                ldmatrix_x4(a[m], base + aBase + m * 16 * ASTRIDE_B + ks * 32);
            #pragma unroll
            for (int n2 = 0; n2 < 2; n2++)
                ldmatrix_x4_t(b0[n2], base + b0Base + n2 * 32 + ks * 16 * BSTRIDE_B);
            #pragma unroll
            for (int m = 0; m < 4; m++) {
                #pragma unroll
                for (int n2 = 0; n2 < 2; n2++) {
                    mma_bf16(acc[m][2 * n2 + 0], a[m], b0[n2][0], b0[n2][1]);
                    mma_bf16(acc[m][2 * n2 + 1], a[m], b0[n2][2], b0[n2][3]);
                }
            }
            if (dual) {
                uint32_t b1[2][4];
                #pragma unroll
                for (int n2 = 0; n2 < 2; n2++)
                    ldmatrix_x4_t(b1[n2], base + b0Base + BBYTES + n2 * 32 + ks * 16 * BSTRIDE_B);
                #pragma unroll
                for (int m = 0; m < 4; m++) {
                    #pragma unroll
                    for (int n2 = 0; n2 < 2; n2++) {
                        mma_bf16(acc[m][2 * n2 + 0], a[m], b1[n2][0], b1[n2][1]);
                        mma_bf16(acc[m][2 * n2 + 1], a[m], b1[n2][2], b1[n2][3]);
                    }
                }
            }
        }
    }

    #pragma unroll
    for (int m = 0; m < 4; m++) {
        int row0 = blkM * 128 + warp_m * 64 + m * 16 + (lane >> 2);
        int row1 = row0 + 8;
        #pragma unroll
        for (int n = 0; n < 4; n++) {
            int col = blkN * 128 + warp_n * 32 + n * 8 + (lane & 3) * 2;
            float bv0 = bias[col], bv1 = bias[col + 1];
            float v0 = acc[m][n][0] + bv0, v1 = acc[m][n][1] + bv1;
            float v2 = acc[m][n][2] + bv0, v3 = acc[m][n][3] + bv1;
            if (relu) {
                v0 = fmaxf(v0, 0.f); v1 = fmaxf(v1, 0.f);
                v2 = fmaxf(v2, 0.f); v3 = fmaxf(v3, 0.f);
            }
            if (row0 < M) {
                if (out) *(float2*)(out + (size_t)row0 * N + col) = make_float2(v0, v1);
                if (selfH) {
                    *(uint32_t*)(selfH + (size_t)row0 * N + col) = pack_hi(v0, v1);
                    *(uint32_t*)(selfL + (size_t)row0 * N + col) = pack_lo(v0, v1);
                }
            }
            if (row1 < M) {
                if (out) *(float2*)(out + (size_t)row1 * N + col) = make_float2(v2, v3);
                if (selfH) {
                    *(uint32_t*)(selfH + (size_t)row1 * N + col) = pack_hi(v2, v3);
                    *(uint32_t*)(selfL + (size_t)row1 * N + col) = pack_lo(v2, v3);
                }
            }
        }
    }
}

// ---------------- host orchestration ----------------
extern "C" void kernel_launch(void* const* d_in, const int* in_sizes, int n_in,
                              void* d_out, int out_size)
{
    const float* x   = (const float*)d_in[0];
    const float* Wn0 = (const float*)d_in[1];
    const float* Ws0 = (const float*)d_in[2];
    const float* b0  = (const float*)d_in[3];
    const float* Wn1 = (const float*)d_in[4];
    const float* Ws1 = (const float*)d_in[5];
    const float* b1  = (const float*)d_in[6];
    const float* Wn2 = (const float*)d_in[7];
    const float* Ws2 = (const float*)d_in[8];
    const float* b2  = (const float*)d_in[9];
    const int* src0 = (const int*)d_in[10];
    const int* dst0 = (const int*)d_in[11];
    const int* src1 = (const int*)d_in[12];
    const int* dst1 = (const int*)d_in[13];
    const int* src2 = (const int*)d_in[14];
    const int* dst2 = (const int*)d_in[15];
    (void)in_sizes; (void)n_in; (void)out_size;

    static cudaStream_t s2 = nullptr;
    static cudaEvent_t ev0 = nullptr, evM = nullptr, evC = nullptr, evG = nullptr;
    if (!s2) {
        cudaStreamCreateWithFlags(&s2, cudaStreamNonBlocking);
        cudaEventCreateWithFlags(&ev0, cudaEventDisableTiming);
        cudaEventCreateWithFlags(&evM, cudaEventDisableTiming);
        cudaEventCreateWithFlags(&evC, cudaEventDisableTiming);
        cudaEventCreateWithFlags(&evG, cudaEventDisableTiming);
        cudaFuncSetAttribute(k_gemm_mma, cudaFuncAttributeMaxDynamicSharedMemorySize, SMEM_TOT);
    }

    __nv_bfloat16 *p_Amh, *p_Aml, *p_iAh, *p_iAl, *p_iBh, *p_iBl, *p_W;
    int *p_deg, *p_b0, *p_b1, *p_b2;
    cudaGetSymbolAddress((void**)&p_Amh, g_Amh);
    cudaGetSymbolAddress((void**)&p_Aml, g_Aml);
    cudaGetSymbolAddress((void**)&p_iAh, g_iAh);
    cudaGetSymbolAddress((void**)&p_iAl, g_iAl);
    cudaGetSymbolAddress((void**)&p_iBh, g_iBh);
    cudaGetSymbolAddress((void**)&p_iBl, g_iBl);
    cudaGetSymbolAddress((void**)&p_W, g_W);
    cudaGetSymbolAddress((void**)&p_deg, g_deg);
    cudaGetSymbolAddress((void**)&p_b0, g_bkt0);
    cudaGetSymbolAddress((void**)&p_b1, g_bkt1);
    cudaGetSymbolAddress((void**)&p_b2, g_bkt2);
    __nv_bfloat16* Wimg[6];
    for (int i = 0; i < 6; i++) Wimg[i] = p_W + (size_t)i * (2 * 256 * 256);

    // ---- fork ----
    cudaEventRecord(ev0, 0);
    cudaStreamWaitEvent(s2, ev0, 0);

    // main: deg zero + bucket0 + agg0 (fp32 x gather)
    cudaMemsetAsync(p_deg, 0, sizeof(int) * NDT, 0);
    cudaEventRecord(evM, 0);
    k_bucket<<<(E0 + 255) / 256, 256>>>(src0, dst0, E0, 0, p_b0);
    k_aggregate_f32<<<(ND0 + 7) / 8, 256>>>(x, p_Amh, p_Aml, p_deg, p_b0, ND0);

    // side: converts (weights + x[:ND0] self image), then buckets 1+2
    k_wconvert_all<<<(4 * 8192 + 2 * 4096 + 255) / 256, 256, 0, s2>>>(Wn0, Ws0, Wn1, Ws1, Wn2, Ws2);
    k_convert<<<(ND0 * 32 + 255) / 256, 256, 0, s2>>>(x, p_iAh, p_iAl, ND0);
    cudaEventRecord(evC, s2);
    cudaStreamWaitEvent(s2, evM, 0);
    k_bucket<<<(E1 + 255) / 256, 256, 0, s2>>>(src1, dst1, E1, ND0, p_b1);
    k_bucket<<<(E2 + 255) / 256, 256, 0, s2>>>(src2, dst2, E2, ND0 + ND1, p_b2);
    cudaEventRecord(evG, s2);

    // main: layer 0 GEMM (needs x self images + weights from evC)
    cudaStreamWaitEvent(0, evC, 0);
    {
        dim3 grid(2, (ND0 + 127) / 128);
        k_gemm_mma<<<grid, 256, SMEM_TOT>>>(p_Amh, p_Aml, p_iAh, p_iAl, Wimg[0], Wimg[1],
                                            b0, nullptr, p_iBh, p_iBl, ND0, 256, 1);
    }
    // main: layers 1,2 (need buckets 1+2 from evG)
    cudaStreamWaitEvent(0, evG, 0);
    k_aggregate_bf16<<<(ND1 + 7) / 8, 256>>>(p_iBh, p_iBl, p_Amh, p_Aml, p_deg + ND0, p_b1, ND1);
    {
        dim3 grid(2, (ND1 + 127) / 128);
        k_gemm_mma<<<grid, 256, SMEM_TOT>>>(p_Amh, p_Aml, p_iBh, p_iBl, Wimg[2], Wimg[3],
                                            b1, nullptr, p_iAh, p_iAl, ND1, 256, 1);
    }
    k_aggregate_bf16<<<(ND2 + 7) / 8, 256>>>(p_iAh, p_iAl, p_Amh, p_Aml, p_deg + ND0 + ND1, p_b2, ND2);
    {
        dim3 grid(1, (ND2 + 127) / 128);
        k_gemm_mma<<<grid, 256, SMEM_TOT>>>(p_Amh, p_Aml, p_iAh, p_iAl, Wimg[4], Wimg[5],
                                            b2, (float*)d_out, nullptr, nullptr, ND2, 128, 0);
    }
}